// round 2
// baseline (speedup 1.0000x reference)
#include <cuda_runtime.h>

#define NTHR   512
#define BT     32
#define HDIM   256
#define EDIM   32
#define TSTEPS 64
#define G3     768
#define KB     8

#define WS_STR 772
#define GS_STR 1036
#define HS_STR 260

#define OFF_HS    0
#define OFF_PREV  8320
#define OFF_GS    9344
#define OFF_WS    42496
#define OFF_BHH   48672
#define OFF_BIH   49440
#define OFF_WH    50208
#define OFF_WB    50464
#define OFF_BASE  50496
#define OFF_BE1   50528
#define OFF_BE2   50784
#define SMEM_FLOATS 51040
#define SMEM_BYTES  (SMEM_FLOATS * 4)

__device__ __forceinline__ unsigned long long pack2(float x) {
    unsigned long long r;
    asm("mov.b64 %0, {%1,%1};" : "=l"(r) : "f"(x));
    return r;
}
__device__ __forceinline__ void fma2(unsigned long long& d, unsigned long long a, unsigned long long b) {
    asm("fma.rn.f32x2 %0, %1, %2, %0;" : "+l"(d) : "l"(a), "l"(b));
}
__device__ __forceinline__ float2 up2(unsigned long long v) {
    float2 f;
    asm("mov.b64 {%0,%1}, %2;" : "=f"(f.x), "=f"(f.y) : "l"(v));
    return f;
}
__device__ __forceinline__ float sigf(float x)  { return 1.0f / (1.0f + __expf(-x)); }
__device__ __forceinline__ float tanhff(float x){ return 1.0f - 2.0f / (__expf(2.0f * x) + 1.0f); }

// out = relu(in @ Wg^T + bias), 32xK @ KxN with N=K=256
__device__ __forceinline__ void encoder_stage(
    const float* __restrict__ in, int instr,
    const float* __restrict__ Wg, const float* __restrict__ bias_s,
    float* __restrict__ outp, float* __restrict__ ws)
{
    const int tid = threadIdx.x;
    const int c0 = (tid & 63) * 4;
    const int r0 = (tid >> 6) * 4;

    unsigned long long acc[4][2];
    {
        unsigned long long bp0 = *(const unsigned long long*)(bias_s + c0);
        unsigned long long bp1 = *(const unsigned long long*)(bias_s + c0 + 2);
        #pragma unroll
        for (int r = 0; r < 4; r++) { acc[r][0] = bp0; acc[r][1] = bp1; }
    }
    for (int kc = 0; kc < HDIM / KB; kc++) {
        __syncthreads();
        for (int i = tid; i < KB * HDIM; i += NTHR) {
            int j = i >> 3, k = i & 7;
            ws[k * 260 + j] = Wg[j * HDIM + kc * KB + k];
        }
        __syncthreads();
        #pragma unroll
        for (int k = 0; k < KB; k++) {
            ulonglong2 w = *(const ulonglong2*)(ws + k * 260 + c0);
            #pragma unroll
            for (int r = 0; r < 4; r++) {
                unsigned long long a = pack2(in[(r0 + r) * instr + kc * KB + k]);
                fma2(acc[r][0], a, w.x);
                fma2(acc[r][1], a, w.y);
            }
        }
    }
    __syncthreads();
    #pragma unroll
    for (int r = 0; r < 4; r++) {
        float2 v0 = up2(acc[r][0]);
        float2 v1 = up2(acc[r][1]);
        float* o = outp + (r0 + r) * HS_STR + c0;
        o[0] = fmaxf(v0.x, 0.f); o[1] = fmaxf(v0.y, 0.f);
        o[2] = fmaxf(v1.x, 0.f); o[3] = fmaxf(v1.y, 0.f);
    }
}

extern __shared__ float smem[];

__global__ void __launch_bounds__(NTHR, 1)
gru_kernel(const float* __restrict__ x,   const int*   __restrict__ targets,
           const float* __restrict__ We1, const float* __restrict__ be1,
           const float* __restrict__ We2, const float* __restrict__ be2,
           const float* __restrict__ Wih, const float* __restrict__ bih,
           const float* __restrict__ Whh, const float* __restrict__ bhh,
           const float* __restrict__ Wdec,const float* __restrict__ bdec,
           float* __restrict__ out)
{
    float* hs     = smem + OFF_HS;
    float* prev   = smem + OFF_PREV;
    float* gs     = smem + OFF_GS;
    float* ws     = smem + OFF_WS;
    float* bhh_s  = smem + OFF_BHH;
    float* bih_s  = smem + OFF_BIH;
    float* wh_s   = smem + OFF_WH;
    float* wb_s   = smem + OFF_WB;
    float* base_s = smem + OFF_BASE;
    float* be1_s  = smem + OFF_BE1;
    float* be2_s  = smem + OFF_BE2;

    const int tid  = threadIdx.x;
    const int row0 = blockIdx.x * BT;

    for (int i = tid; i < G3; i += NTHR) { bhh_s[i] = bhh[i]; bih_s[i] = bih[i]; }
    for (int i = tid; i < HDIM; i += NTHR) {
        wh_s[i] = Wdec[i]; be1_s[i] = be1[i]; be2_s[i] = be2[i];
    }
    if (tid < EDIM) wb_s[tid] = Wdec[HDIM + tid];
    const float b0 = bdec[0];

    for (int i = tid; i < BT * HDIM; i += NTHR) {
        int r = i >> 8, c = i & 255;
        gs[r * GS_STR + c] = x[(row0 + r) * HDIM + c];
    }
    for (int i = tid; i < BT * EDIM; i += NTHR) prev[i] = 0.0f;
    __syncthreads();

    encoder_stage(gs, GS_STR, We1, be1_s, hs, ws);
    encoder_stage(hs, HS_STR, We2, be2_s, hs, ws);

    const int c0g  = (tid & 63) * 12;
    const int r0g  = (tid >> 6) * 4;
    const int wid  = tid >> 5;
    const int lane = tid & 31;

    for (int t = 0; t < TSTEPS; t++) {
        // phase 1a: gh = h @ Whh^T + bhh
        unsigned long long acc[4][6];
        #pragma unroll
        for (int p = 0; p < 6; p++) {
            unsigned long long bp = *(const unsigned long long*)(bhh_s + c0g + 2 * p);
            #pragma unroll
            for (int r = 0; r < 4; r++) acc[r][p] = bp;
        }
        for (int kc = 0; kc < HDIM / KB; kc++) {
            __syncthreads();
            for (int i = tid; i < KB * G3; i += NTHR) {
                int j = i >> 3, k = i & 7;
                ws[k * WS_STR + j] = Whh[j * HDIM + kc * KB + k];
            }
            __syncthreads();
            #pragma unroll
            for (int k = 0; k < KB; k++) {
                const float* wrow = ws + k * WS_STR + c0g;
                ulonglong2 w0 = *(const ulonglong2*)(wrow);
                ulonglong2 w1 = *(const ulonglong2*)(wrow + 4);
                ulonglong2 w2 = *(const ulonglong2*)(wrow + 8);
                #pragma unroll
                for (int r = 0; r < 4; r++) {
                    unsigned long long a = pack2(hs[(r0g + r) * HS_STR + kc * KB + k]);
                    fma2(acc[r][0], a, w0.x); fma2(acc[r][1], a, w0.y);
                    fma2(acc[r][2], a, w1.x); fma2(acc[r][3], a, w1.y);
                    fma2(acc[r][4], a, w2.x); fma2(acc[r][5], a, w2.y);
                }
            }
        }
        #pragma unroll
        for (int r = 0; r < 4; r++) {
            float* grow = gs + (r0g + r) * GS_STR;
            #pragma unroll
            for (int p = 0; p < 6; p++) {
                float2 v = up2(acc[r][p]);
                grow[c0g + 2 * p]     = v.x;
                grow[c0g + 2 * p + 1] = v.y;
            }
        }

        // phase 1b: gi = prev @ Wih^T + bih, merged into gs
        {
            float gi[4][12];
            #pragma unroll
            for (int c = 0; c < 12; c++) {
                float bv = bih_s[c0g + c];
                #pragma unroll
                for (int r = 0; r < 4; r++) gi[r][c] = bv;
            }
            #pragma unroll
            for (int e4 = 0; e4 < 8; e4++) {
                float4 p[4];
                #pragma unroll
                for (int r = 0; r < 4; r++)
                    p[r] = *(const float4*)(prev + (r0g + r) * EDIM + e4 * 4);
                #pragma unroll
                for (int c = 0; c < 12; c++) {
                    float4 w = *(const float4*)(Wih + (c0g + c) * EDIM + e4 * 4);
                    #pragma unroll
                    for (int r = 0; r < 4; r++)
                        gi[r][c] += p[r].x * w.x + p[r].y * w.y + p[r].z * w.z + p[r].w * w.w;
                }
            }
            #pragma unroll
            for (int r = 0; r < 4; r++) {
                float* grow = gs + (r0g + r) * GS_STR;
                #pragma unroll
                for (int c = 0; c < 12; c++) {
                    int j = c0g + c;
                    if (j < 512) grow[j] += gi[r][c];
                    else         grow[j + 256] = gi[r][c];
                }
            }
        }
        __syncthreads();

        // phase 2: gates, h update, base = h_new . w_h + b0
        {
            const int row = tid >> 4;
            const int cb  = tid & 15;
            const float* grow = gs + row * GS_STR;
            float* hrow = hs + row * HS_STR;
            float psum = 0.0f;
            #pragma unroll
            for (int i = 0; i < 16; i++) {
                int c = cb + 16 * i;
                float rg = sigf(grow[c]);
                float zg = sigf(grow[c + 256]);
                float n  = tanhff(grow[c + 768] + rg * grow[c + 512]);
                float hnew = n + zg * (hrow[c] - n);
                hrow[c] = hnew;
                psum += hnew * wh_s[c];
            }
            #pragma unroll
            for (int o = 8; o >= 1; o >>= 1)
                psum += __shfl_down_sync(0xffffffffu, psum, o, 16);
            if (cb == 0) base_s[row] = psum + b0;
        }
        __syncthreads();

        // phase 3: logits = base + exclusive cumsum(t_bits * w_b)
        #pragma unroll
        for (int rr = 0; rr < 2; rr++) {
            int row = 2 * wid + rr;
            int idx = ((row0 + row) * TSTEPS + t) * EDIM + lane;
            float wbv = (float)targets[idx] * wb_s[lane];
            float v = wbv;
            #pragma unroll
            for (int o = 1; o < 32; o <<= 1) {
                float u = __shfl_up_sync(0xffffffffu, v, o);
                if (lane >= o) v += u;
            }
            float logit = base_s[row] + (v - wbv);
            out[idx] = logit;
            prev[row * EDIM + lane] = logit;
        }
        __syncthreads();
    }
}

extern "C" void kernel_launch(void* const* d_in, const int* in_sizes, int n_in,
                              void* d_out, int out_size)
{
    cudaFuncSetAttribute(gru_kernel, cudaFuncAttributeMaxDynamicSharedMemorySize, SMEM_BYTES);
    gru_kernel<<<4096 / BT, NTHR, SMEM_BYTES>>>(
        (const float*)d_in[0], (const int*)d_in[1],
        (const float*)d_in[2], (const float*)d_in[3],
        (const float*)d_in[4], (const float*)d_in[5],
        (const float*)d_in[6], (const float*)d_in[7],
        (const float*)d_in[8], (const float*)d_in[9],
        (const float*)d_in[10], (const float*)d_in[11],
        (float*)d_out);
}

// round 3
// speedup vs baseline: 5.8753x; 5.8753x over previous
#include <cuda_runtime.h>
#include <cuda_bf16.h>

#define NTHR   512
#define BT     32
#define HDIM   256
#define EDIM   32
#define TSTEPS 64
#define G3     768
#define KB     8
#define KCAT   288
#define NKT    18      // k16 tiles
#define NNT    96      // n8 tiles

#define HS_STR 260
#define GS_STR 1036
#define A_STR  145     // u32 stride for bf16x2 A rows (144 used + 1 pad)

// smem offsets (floats)
#define OFF_HS    0
#define OFF_PREV  8320
#define OFF_GS    9344
#define OFF_AHI   42496
#define OFF_ALO   47136
#define OFF_BSUM  51776
#define OFF_BHH   52544
#define OFF_BIH   53312
#define OFF_WH    54080
#define OFF_WB    54336
#define OFF_BASE  54368
#define OFF_BE1   54400
#define OFF_BE2   54656
#define SMEM_FLOATS 54912
#define SMEM_BYTES  (SMEM_FLOATS * 4)

// W fragment buffers: [tk][tn][lane][2] u32 (bf16x2), hi and lo
__device__ unsigned g_wfrag_hi[NKT * NNT * 64];
__device__ unsigned g_wfrag_lo[NKT * NNT * 64];

__device__ __forceinline__ unsigned long long pack2(float x) {
    unsigned long long r; asm("mov.b64 %0, {%1,%1};" : "=l"(r) : "f"(x)); return r;
}
__device__ __forceinline__ void fma2(unsigned long long& d, unsigned long long a, unsigned long long b) {
    asm("fma.rn.f32x2 %0, %1, %2, %0;" : "+l"(d) : "l"(a), "l"(b));
}
__device__ __forceinline__ float2 up2(unsigned long long v) {
    float2 f; asm("mov.b64 {%0,%1}, %2;" : "=f"(f.x), "=f"(f.y) : "l"(v)); return f;
}
__device__ __forceinline__ float sigf(float x)  { return 1.0f / (1.0f + __expf(-x)); }
__device__ __forceinline__ float tanhff(float x){ return 1.0f - 2.0f / (__expf(2.0f * x) + 1.0f); }

__device__ __forceinline__ void mma_bf16(float* c, const unsigned* a, unsigned b0, unsigned b1) {
    asm("mma.sync.aligned.m16n8k16.row.col.f32.bf16.bf16.f32 "
        "{%0,%1,%2,%3},{%4,%5,%6,%7},{%8,%9},{%0,%1,%2,%3};"
        : "+f"(c[0]), "+f"(c[1]), "+f"(c[2]), "+f"(c[3])
        : "r"(a[0]), "r"(a[1]), "r"(a[2]), "r"(a[3]), "r"(b0), "r"(b1));
}

// ---------- prep: build bf16 hi/lo B-fragments of Wcat = [Whh | Wih] ----------
__global__ void prep_kernel(const float* __restrict__ Whh, const float* __restrict__ Wih) {
    int idx = blockIdx.x * blockDim.x + threadIdx.x;
    if (idx >= NKT * NNT * 32) return;
    int l    = idx & 31;
    int tile = idx >> 5;
    int tn   = tile % NNT;
    int tk   = tile / NNT;
    int n    = tn * 8 + (l >> 2);          // output row j of Wcat (768)
    int kb   = tk * 16 + (l & 3) * 2;

    float v[4];
    #pragma unroll
    for (int q = 0; q < 4; q++) {
        int k = kb + (q & 1) + (q >> 1) * 8;
        v[q] = (k < HDIM) ? Whh[n * HDIM + k] : Wih[n * EDIM + (k - HDIM)];
    }
    unsigned hp[2], lp[2];
    #pragma unroll
    for (int p = 0; p < 2; p++) {
        __nv_bfloat16 h0 = __float2bfloat16_rn(v[p * 2]);
        __nv_bfloat16 h1 = __float2bfloat16_rn(v[p * 2 + 1]);
        float l0 = v[p * 2]     - __bfloat162float(h0);
        float l1 = v[p * 2 + 1] - __bfloat162float(h1);
        __nv_bfloat16 g0 = __float2bfloat16_rn(l0);
        __nv_bfloat16 g1 = __float2bfloat16_rn(l1);
        hp[p] = (unsigned)__bfloat16_as_ushort(h0) | ((unsigned)__bfloat16_as_ushort(h1) << 16);
        lp[p] = (unsigned)__bfloat16_as_ushort(g0) | ((unsigned)__bfloat16_as_ushort(g1) << 16);
    }
    int base = tile * 64 + l * 2;
    g_wfrag_hi[base] = hp[0]; g_wfrag_hi[base + 1] = hp[1];
    g_wfrag_lo[base] = lp[0]; g_wfrag_lo[base + 1] = lp[1];
}

// ---------- encoder stage (fp32, runs once) ----------
__device__ __forceinline__ void encoder_stage(
    const float* __restrict__ in, int instr,
    const float* __restrict__ Wg, const float* __restrict__ bias_s,
    float* __restrict__ outp, float* __restrict__ ws)
{
    const int tid = threadIdx.x;
    const int c0 = (tid & 63) * 4;
    const int r0 = (tid >> 6) * 4;
    unsigned long long acc[4][2];
    {
        unsigned long long bp0 = *(const unsigned long long*)(bias_s + c0);
        unsigned long long bp1 = *(const unsigned long long*)(bias_s + c0 + 2);
        #pragma unroll
        for (int r = 0; r < 4; r++) { acc[r][0] = bp0; acc[r][1] = bp1; }
    }
    for (int kc = 0; kc < HDIM / KB; kc++) {
        __syncthreads();
        for (int i = tid; i < KB * HDIM; i += NTHR) {
            int j = i >> 3, k = i & 7;
            ws[k * 260 + j] = Wg[j * HDIM + kc * KB + k];
        }
        __syncthreads();
        #pragma unroll
        for (int k = 0; k < KB; k++) {
            ulonglong2 w = *(const ulonglong2*)(ws + k * 260 + c0);
            #pragma unroll
            for (int r = 0; r < 4; r++) {
                unsigned long long a = pack2(in[(r0 + r) * instr + kc * KB + k]);
                fma2(acc[r][0], a, w.x);
                fma2(acc[r][1], a, w.y);
            }
        }
    }
    __syncthreads();
    #pragma unroll
    for (int r = 0; r < 4; r++) {
        float2 v0 = up2(acc[r][0]);
        float2 v1 = up2(acc[r][1]);
        float* o = outp + (r0 + r) * HS_STR + c0;
        o[0] = fmaxf(v0.x, 0.f); o[1] = fmaxf(v0.y, 0.f);
        o[2] = fmaxf(v1.x, 0.f); o[3] = fmaxf(v1.y, 0.f);
    }
}

extern __shared__ float smem[];

__global__ void __launch_bounds__(NTHR, 1)
gru_kernel(const float* __restrict__ x,   const int*   __restrict__ targets,
           const float* __restrict__ We1, const float* __restrict__ be1,
           const float* __restrict__ We2, const float* __restrict__ be2,
           const float* __restrict__ Wih, const float* __restrict__ bih,
           const float* __restrict__ Whh, const float* __restrict__ bhh,
           const float* __restrict__ Wdec,const float* __restrict__ bdec,
           float* __restrict__ out)
{
    float* hs     = smem + OFF_HS;
    float* prev   = smem + OFF_PREV;
    float* gs     = smem + OFF_GS;
    unsigned* A32h = (unsigned*)(smem + OFF_AHI);
    unsigned* A32l = (unsigned*)(smem + OFF_ALO);
    float* bsum_s = smem + OFF_BSUM;
    float* bhh_s  = smem + OFF_BHH;
    float* bih_s  = smem + OFF_BIH;
    float* wh_s   = smem + OFF_WH;
    float* wb_s   = smem + OFF_WB;
    float* base_s = smem + OFF_BASE;
    float* be1_s  = smem + OFF_BE1;
    float* be2_s  = smem + OFF_BE2;

    const int tid  = threadIdx.x;
    const int row0 = blockIdx.x * BT;
    const int wid  = tid >> 5;
    const int lane = tid & 31;

    for (int i = tid; i < G3; i += NTHR) {
        float a = bhh[i], b = bih[i];
        bhh_s[i] = a; bih_s[i] = b; bsum_s[i] = a + b;
    }
    for (int i = tid; i < HDIM; i += NTHR) {
        wh_s[i] = Wdec[i]; be1_s[i] = be1[i]; be2_s[i] = be2[i];
    }
    if (tid < EDIM) wb_s[tid] = Wdec[HDIM + tid];
    const float b0 = bdec[0];

    for (int i = tid; i < BT * HDIM; i += NTHR) {
        int r = i >> 8, c = i & 255;
        gs[r * GS_STR + c] = x[(row0 + r) * HDIM + c];
    }
    for (int i = tid; i < BT * EDIM; i += NTHR) prev[i] = 0.0f;
    __syncthreads();

    // encoder (scratch aliases A buffers, unused yet)
    encoder_stage(gs, GS_STR, We1, be1_s, hs, (float*)A32h);
    encoder_stage(hs, HS_STR, We2, be2_s, hs, (float*)A32h);
    __syncthreads();

    const int l4 = lane >> 2;
    const int l2 = (lane & 3) * 2;

    for (int t = 0; t < TSTEPS; t++) {
        // ---- A conversion: [h | prev] fp32 -> bf16 hi/lo ----
        #pragma unroll
        for (int ii = 0; ii < 9; ii++) {
            int i = tid + ii * NTHR;          // 0 .. 4607
            int r = i / 144, cu = i - r * 144;
            int k = cu * 2;
            float x0, x1;
            if (k < HDIM) { x0 = hs[r * HS_STR + k]; x1 = hs[r * HS_STR + k + 1]; }
            else          { x0 = prev[r * EDIM + k - HDIM]; x1 = prev[r * EDIM + k - HDIM + 1]; }
            __nv_bfloat16 h0 = __float2bfloat16_rn(x0);
            __nv_bfloat16 h1 = __float2bfloat16_rn(x1);
            __nv_bfloat16 g0 = __float2bfloat16_rn(x0 - __bfloat162float(h0));
            __nv_bfloat16 g1 = __float2bfloat16_rn(x1 - __bfloat162float(h1));
            A32h[r * A_STR + cu] = (unsigned)__bfloat16_as_ushort(h0) | ((unsigned)__bfloat16_as_ushort(h1) << 16);
            A32l[r * A_STR + cu] = (unsigned)__bfloat16_as_ushort(g0) | ((unsigned)__bfloat16_as_ushort(g1) << 16);
        }
        __syncthreads();

        // ---- fused GEMM: gates = [h|prev] @ Wcat^T + biases (3x-bf16 mma) ----
        {
            float acc[6][2][4];
            #pragma unroll
            for (int i = 0; i < 6; i++) {
                int n0 = (wid + 16 * i) * 8 + l2;
                float v0 = (i < 4) ? bsum_s[n0]     : bhh_s[n0];
                float v1 = (i < 4) ? bsum_s[n0 + 1] : bhh_s[n0 + 1];
                #pragma unroll
                for (int m = 0; m < 2; m++) {
                    acc[i][m][0] = v0; acc[i][m][1] = v1;
                    acc[i][m][2] = v0; acc[i][m][3] = v1;
                }
            }
            // main k-tiles 0..15 (h part): all targets = acc
            #pragma unroll 4
            for (int tk = 0; tk < 16; tk++) {
                unsigned ah[2][4], al[2][4];
                int colu = tk * 8 + (lane & 3);
                #pragma unroll
                for (int m = 0; m < 2; m++) {
                    int r0 = (m * 16 + l4) * A_STR + colu;
                    int r1 = r0 + 8 * A_STR;
                    ah[m][0] = A32h[r0]; ah[m][1] = A32h[r1];
                    ah[m][2] = A32h[r0 + 4]; ah[m][3] = A32h[r1 + 4];
                    al[m][0] = A32l[r0]; al[m][1] = A32l[r1];
                    al[m][2] = A32l[r0 + 4]; al[m][3] = A32l[r1 + 4];
                }
                #pragma unroll
                for (int i = 0; i < 6; i++) {
                    int off = ((tk * NNT + (wid + 16 * i)) * 32 + lane) * 2;
                    uint2 bh = *(const uint2*)(g_wfrag_hi + off);
                    uint2 bl = *(const uint2*)(g_wfrag_lo + off);
                    #pragma unroll
                    for (int m = 0; m < 2; m++) {
                        mma_bf16(acc[i][m], ah[m], bh.x, bh.y);
                        mma_bf16(acc[i][m], ah[m], bl.x, bl.y);
                        mma_bf16(acc[i][m], al[m], bh.x, bh.y);
                    }
                }
            }
            // gi accumulators for separate tiles (n >= 512)
            float accg[2][2][4];
            #pragma unroll
            for (int i = 0; i < 2; i++) {
                int n0 = (wid + 16 * (4 + i)) * 8 + l2;
                float v0 = bih_s[n0], v1 = bih_s[n0 + 1];
                #pragma unroll
                for (int m = 0; m < 2; m++) {
                    accg[i][m][0] = v0; accg[i][m][1] = v1;
                    accg[i][m][2] = v0; accg[i][m][3] = v1;
                }
            }
            // tail k-tiles 16,17 (prev part): i<4 -> acc, i>=4 -> accg
            #pragma unroll
            for (int tt = 0; tt < 2; tt++) {
                int tk = 16 + tt;
                unsigned ah[2][4], al[2][4];
                int colu = tk * 8 + (lane & 3);
                #pragma unroll
                for (int m = 0; m < 2; m++) {
                    int r0 = (m * 16 + l4) * A_STR + colu;
                    int r1 = r0 + 8 * A_STR;
                    ah[m][0] = A32h[r0]; ah[m][1] = A32h[r1];
                    ah[m][2] = A32h[r0 + 4]; ah[m][3] = A32h[r1 + 4];
                    al[m][0] = A32l[r0]; al[m][1] = A32l[r1];
                    al[m][2] = A32l[r0 + 4]; al[m][3] = A32l[r1 + 4];
                }
                #pragma unroll
                for (int i = 0; i < 6; i++) {
                    int off = ((tk * NNT + (wid + 16 * i)) * 32 + lane) * 2;
                    uint2 bh = *(const uint2*)(g_wfrag_hi + off);
                    uint2 bl = *(const uint2*)(g_wfrag_lo + off);
                    #pragma unroll
                    for (int m = 0; m < 2; m++) {
                        float* T = (i < 4) ? acc[i][m] : accg[i - 4][m];
                        mma_bf16(T, ah[m], bh.x, bh.y);
                        mma_bf16(T, ah[m], bl.x, bl.y);
                        mma_bf16(T, al[m], bh.x, bh.y);
                    }
                }
            }
            // store gates to gs
            #pragma unroll
            for (int i = 0; i < 6; i++) {
                int n0 = (wid + 16 * i) * 8 + l2;
                #pragma unroll
                for (int m = 0; m < 2; m++) {
                    int row = m * 16 + l4;
                    float* g0 = gs + row * GS_STR + n0;
                    float* g1 = gs + (row + 8) * GS_STR + n0;
                    g0[0] = acc[i][m][0]; g0[1] = acc[i][m][1];
                    g1[0] = acc[i][m][2]; g1[1] = acc[i][m][3];
                    if (i >= 4) {  // gi stored at +256 (inn slot)
                        g0[256] = accg[i - 4][m][0]; g0[257] = accg[i - 4][m][1];
                        g1[256] = accg[i - 4][m][2]; g1[257] = accg[i - 4][m][3];
                    }
                }
            }
        }
        __syncthreads();

        // ---- phase 2: gates, h update, base ----
        {
            const int row = tid >> 4;
            const int cb  = tid & 15;
            const float* grow = gs + row * GS_STR;
            float* hrow = hs + row * HS_STR;
            float psum = 0.0f;
            #pragma unroll
            for (int i = 0; i < 16; i++) {
                int c = cb + 16 * i;
                float rg = sigf(grow[c]);
                float zg = sigf(grow[c + 256]);
                float n  = tanhff(grow[c + 768] + rg * grow[c + 512]);
                float hnew = n + zg * (hrow[c] - n);
                hrow[c] = hnew;
                psum += hnew * wh_s[c];
            }
            #pragma unroll
            for (int o = 8; o >= 1; o >>= 1)
                psum += __shfl_down_sync(0xffffffffu, psum, o, 16);
            if (cb == 0) base_s[row] = psum + b0;
        }
        __syncthreads();

        // ---- phase 3: logits ----
        #pragma unroll
        for (int rr = 0; rr < 2; rr++) {
            int row = 2 * wid + rr;
            int idx = ((row0 + row) * TSTEPS + t) * EDIM + lane;
            float wbv = (float)targets[idx] * wb_s[lane];
            float v = wbv;
            #pragma unroll
            for (int o = 1; o < 32; o <<= 1) {
                float u = __shfl_up_sync(0xffffffffu, v, o);
                if (lane >= o) v += u;
            }
            float logit = base_s[row] + (v - wbv);
            out[idx] = logit;
            prev[row * EDIM + lane] = logit;
        }
        __syncthreads();
    }
}

extern "C" void kernel_launch(void* const* d_in, const int* in_sizes, int n_in,
                              void* d_out, int out_size)
{
    prep_kernel<<<(NKT * NNT * 32 + 255) / 256, 256>>>(
        (const float*)d_in[8], (const float*)d_in[6]);

    cudaFuncSetAttribute(gru_kernel, cudaFuncAttributeMaxDynamicSharedMemorySize, SMEM_BYTES);
    gru_kernel<<<4096 / BT, NTHR, SMEM_BYTES>>>(
        (const float*)d_in[0], (const int*)d_in[1],
        (const float*)d_in[2], (const float*)d_in[3],
        (const float*)d_in[4], (const float*)d_in[5],
        (const float*)d_in[6], (const float*)d_in[7],
        (const float*)d_in[8], (const float*)d_in[9],
        (const float*)d_in[10], (const float*)d_in[11],
        (float*)d_out);
}

// round 5
// speedup vs baseline: 6.3815x; 1.0862x over previous
#include <cuda_runtime.h>
#include <cuda_bf16.h>

#define NTHR   512
#define BT     32
#define HDIM   256
#define EDIM   32
#define TSTEPS 64
#define G3     768
#define KB     8
#define NKT    18
#define NNT    96

#define HS_STR 260
#define GS_STR 1036
#define A_PITCH 296            // bf16 elems per A row
#define A_U32   148            // u32 per A row

// smem offsets (floats)
#define OFF_HS    0            // 32*260   = 8320
#define OFF_GS    8320         // 32*1036  = 33152
#define OFF_AHI   41472        // 32*148   = 4736
#define OFF_ALO   46208        // 4736
#define OFF_BSUM  50944        // 768
#define OFF_BHH   51712        // 768
#define OFF_BIH   52480        // 768
#define OFF_WH    53248        // 256
#define OFF_WB    53504        // 32
#define OFF_BASE  53536        // 32
#define OFF_BE1   53568        // 256
#define OFF_BE2   53824        // 256
#define SMEM_FLOATS 54080
#define SMEM_BYTES  (SMEM_FLOATS * 4)   // 216320 bytes

// interleaved W fragments: per (tk,tn,lane): {bh0,bh1,bl0,bl1}
__device__ uint4 g_wfrag[NKT * NNT * 32];

__device__ __forceinline__ unsigned long long pack2(float x) {
    unsigned long long r; asm("mov.b64 %0, {%1,%1};" : "=l"(r) : "f"(x)); return r;
}
__device__ __forceinline__ void fma2(unsigned long long& d, unsigned long long a, unsigned long long b) {
    asm("fma.rn.f32x2 %0, %1, %2, %0;" : "+l"(d) : "l"(a), "l"(b));
}
__device__ __forceinline__ float2 up2(unsigned long long v) {
    float2 f; asm("mov.b64 {%0,%1}, %2;" : "=f"(f.x), "=f"(f.y) : "l"(v)); return f;
}
__device__ __forceinline__ float sigf(float x)  { return 1.0f / (1.0f + __expf(-x)); }
__device__ __forceinline__ float tanhff(float x){ return 1.0f - 2.0f / (__expf(2.0f * x) + 1.0f); }

__device__ __forceinline__ void mma_bf16(float* c, const unsigned* a, unsigned b0, unsigned b1) {
    asm("mma.sync.aligned.m16n8k16.row.col.f32.bf16.bf16.f32 "
        "{%0,%1,%2,%3},{%4,%5,%6,%7},{%8,%9},{%0,%1,%2,%3};"
        : "+f"(c[0]), "+f"(c[1]), "+f"(c[2]), "+f"(c[3])
        : "r"(a[0]), "r"(a[1]), "r"(a[2]), "r"(a[3]), "r"(b0), "r"(b1));
}
__device__ __forceinline__ void ldmat_x4(unsigned* r, unsigned addr) {
    asm volatile("ldmatrix.sync.aligned.m8n8.x4.shared.b16 {%0,%1,%2,%3}, [%4];"
        : "=r"(r[0]), "=r"(r[1]), "=r"(r[2]), "=r"(r[3]) : "r"(addr));
}
__device__ __forceinline__ unsigned packbf(float a, float b) {
    __nv_bfloat16 ha = __float2bfloat16_rn(a), hb = __float2bfloat16_rn(b);
    return (unsigned)__bfloat16_as_ushort(ha) | ((unsigned)__bfloat16_as_ushort(hb) << 16);
}
__device__ __forceinline__ void split2(float a, float b, unsigned& hi, unsigned& lo) {
    __nv_bfloat16 ha = __float2bfloat16_rn(a), hb = __float2bfloat16_rn(b);
    hi = (unsigned)__bfloat16_as_ushort(ha) | ((unsigned)__bfloat16_as_ushort(hb) << 16);
    lo = packbf(a - __bfloat162float(ha), b - __bfloat162float(hb));
}

// ---------- prep: interleaved bf16 hi/lo B-fragments of Wcat = [Whh | Wih] ----------
__global__ void prep_kernel(const float* __restrict__ Whh, const float* __restrict__ Wih) {
    int idx = blockIdx.x * blockDim.x + threadIdx.x;
    if (idx >= NKT * NNT * 32) return;
    int l    = idx & 31;
    int tile = idx >> 5;
    int tn   = tile % NNT;
    int tk   = tile / NNT;
    int n    = tn * 8 + (l >> 2);
    int kb   = tk * 16 + (l & 3) * 2;

    float v[4];
    #pragma unroll
    for (int q = 0; q < 4; q++) {
        int k = kb + (q & 1) + (q >> 1) * 8;
        v[q] = (k < HDIM) ? Whh[n * HDIM + k] : Wih[n * EDIM + (k - HDIM)];
    }
    uint4 o;
    split2(v[0], v[1], o.x, o.z);
    split2(v[2], v[3], o.y, o.w);
    g_wfrag[idx] = o;
}

// ---------- encoder stage (fp32, runs once) ----------
__device__ __forceinline__ void encoder_stage(
    const float* __restrict__ in, int instr,
    const float* __restrict__ Wg, const float* __restrict__ bias_s,
    float* __restrict__ outp, float* __restrict__ ws)
{
    const int tid = threadIdx.x;
    const int c0 = (tid & 63) * 4;
    const int r0 = (tid >> 6) * 4;
    unsigned long long acc[4][2];
    {
        unsigned long long bp0 = *(const unsigned long long*)(bias_s + c0);
        unsigned long long bp1 = *(const unsigned long long*)(bias_s + c0 + 2);
        #pragma unroll
        for (int r = 0; r < 4; r++) { acc[r][0] = bp0; acc[r][1] = bp1; }
    }
    for (int kc = 0; kc < HDIM / KB; kc++) {
        __syncthreads();
        for (int i = tid; i < KB * HDIM; i += NTHR) {
            int j = i >> 3, k = i & 7;
            ws[k * 260 + j] = Wg[j * HDIM + kc * KB + k];
        }
        __syncthreads();
        #pragma unroll
        for (int k = 0; k < KB; k++) {
            ulonglong2 w = *(const ulonglong2*)(ws + k * 260 + c0);
            #pragma unroll
            for (int r = 0; r < 4; r++) {
                unsigned long long a = pack2(in[(r0 + r) * instr + kc * KB + k]);
                fma2(acc[r][0], a, w.x);
                fma2(acc[r][1], a, w.y);
            }
        }
    }
    __syncthreads();
    #pragma unroll
    for (int r = 0; r < 4; r++) {
        float2 v0 = up2(acc[r][0]);
        float2 v1 = up2(acc[r][1]);
        float* o = outp + (r0 + r) * HS_STR + c0;
        o[0] = fmaxf(v0.x, 0.f); o[1] = fmaxf(v0.y, 0.f);
        o[2] = fmaxf(v1.x, 0.f); o[3] = fmaxf(v1.y, 0.f);
    }
}

extern __shared__ float smem[];

__global__ void __launch_bounds__(NTHR, 1)
gru_kernel(const float* __restrict__ x,   const int*   __restrict__ targets,
           const float* __restrict__ We1, const float* __restrict__ be1,
           const float* __restrict__ We2, const float* __restrict__ be2,
           const float* __restrict__ Wih, const float* __restrict__ bih,
           const float* __restrict__ Whh, const float* __restrict__ bhh,
           const float* __restrict__ Wdec,const float* __restrict__ bdec,
           float* __restrict__ out)
{
    float* hs     = smem + OFF_HS;
    float* gs     = smem + OFF_GS;
    unsigned* Ah32 = (unsigned*)(smem + OFF_AHI);
    unsigned* Al32 = (unsigned*)(smem + OFF_ALO);
    float* bsum_s = smem + OFF_BSUM;
    float* bhh_s  = smem + OFF_BHH;
    float* bih_s  = smem + OFF_BIH;
    float* wh_s   = smem + OFF_WH;
    float* wb_s   = smem + OFF_WB;
    float* base_s = smem + OFF_BASE;
    float* be1_s  = smem + OFF_BE1;
    float* be2_s  = smem + OFF_BE2;

    const int tid  = threadIdx.x;
    const int row0 = blockIdx.x * BT;
    const int wid  = tid >> 5;
    const int lane = tid & 31;

    for (int i = tid; i < G3; i += NTHR) {
        float a = bhh[i], b = bih[i];
        bhh_s[i] = a; bih_s[i] = b; bsum_s[i] = a + b;
    }
    for (int i = tid; i < HDIM; i += NTHR) {
        wh_s[i] = Wdec[i]; be1_s[i] = be1[i]; be2_s[i] = be2[i];
    }
    if (tid < EDIM) wb_s[tid] = Wdec[HDIM + tid];
    const float b0 = bdec[0];

    for (int i = tid; i < BT * HDIM; i += NTHR) {
        int r = i >> 8, c = i & 255;
        gs[r * GS_STR + c] = x[(row0 + r) * HDIM + c];
    }
    __syncthreads();

    // encoder (scratch aliases A planes; A is filled only after this)
    encoder_stage(gs, GS_STR, We1, be1_s, hs, (float*)Ah32);
    encoder_stage(hs, HS_STR, We2, be2_s, hs, (float*)Ah32);
    __syncthreads();

    // initial A: h0 bf16 hi/lo, prev = 0, pad = 0
    for (int i = tid; i < BT * A_U32; i += NTHR) {
        int r = i / A_U32, cu = i - r * A_U32;
        unsigned hi = 0, lo = 0;
        if (cu < 128) split2(hs[r * HS_STR + 2 * cu], hs[r * HS_STR + 2 * cu + 1], hi, lo);
        Ah32[r * A_U32 + cu] = hi;
        Al32[r * A_U32 + cu] = lo;
    }
    __syncthreads();

    const int l4 = lane >> 2;
    const int l2 = (lane & 3) * 2;
    const unsigned aoff = (unsigned)((lane & 15) * A_PITCH + (lane >> 4) * 8) * 2u;
    const unsigned ahi_base = (unsigned)__cvta_generic_to_shared(Ah32) + aoff;
    const unsigned alo_base = (unsigned)__cvta_generic_to_shared(Al32) + aoff;

    for (int t = 0; t < TSTEPS; t++) {
        // ================= GEMM: gates = [h|prev] @ Wcat^T + biases =================
        {
            float acc[6][2][4];
            #pragma unroll
            for (int i = 0; i < 6; i++) {
                int n0 = (wid + 16 * i) * 8 + l2;
                float v0 = (i < 4) ? bsum_s[n0]     : bhh_s[n0];
                float v1 = (i < 4) ? bsum_s[n0 + 1] : bhh_s[n0 + 1];
                #pragma unroll
                for (int m = 0; m < 2; m++) {
                    acc[i][m][0] = v0; acc[i][m][1] = v1;
                    acc[i][m][2] = v0; acc[i][m][3] = v1;
                }
            }
            #pragma unroll 2
            for (int tk = 0; tk < 16; tk++) {
                unsigned ah[2][4], al[2][4];
                #pragma unroll
                for (int m = 0; m < 2; m++) {
                    unsigned off = (unsigned)(m * 16 * A_PITCH + tk * 16) * 2u;
                    ldmat_x4(ah[m], ahi_base + off);
                    ldmat_x4(al[m], alo_base + off);
                }
                #pragma unroll
                for (int i = 0; i < 6; i++) {
                    uint4 b = g_wfrag[(tk * NNT + wid + 16 * i) * 32 + lane];
                    #pragma unroll
                    for (int m = 0; m < 2; m++) {
                        mma_bf16(acc[i][m], ah[m], b.x, b.y);
                        mma_bf16(acc[i][m], ah[m], b.z, b.w);
                        mma_bf16(acc[i][m], al[m], b.x, b.y);
                    }
                }
            }
            float accg[2][2][4];
            #pragma unroll
            for (int i = 0; i < 2; i++) {
                int n0 = (wid + 16 * (4 + i)) * 8 + l2;
                float v0 = bih_s[n0], v1 = bih_s[n0 + 1];
                #pragma unroll
                for (int m = 0; m < 2; m++) {
                    accg[i][m][0] = v0; accg[i][m][1] = v1;
                    accg[i][m][2] = v0; accg[i][m][3] = v1;
                }
            }
            #pragma unroll
            for (int tt = 0; tt < 2; tt++) {
                int tk = 16 + tt;
                unsigned ah[2][4], al[2][4];
                #pragma unroll
                for (int m = 0; m < 2; m++) {
                    unsigned off = (unsigned)(m * 16 * A_PITCH + tk * 16) * 2u;
                    ldmat_x4(ah[m], ahi_base + off);
                    ldmat_x4(al[m], alo_base + off);
                }
                #pragma unroll
                for (int i = 0; i < 6; i++) {
                    uint4 b = g_wfrag[(tk * NNT + wid + 16 * i) * 32 + lane];
                    #pragma unroll
                    for (int m = 0; m < 2; m++) {
                        float* T = (i < 4) ? acc[i][m] : accg[i - 4][m];
                        mma_bf16(T, ah[m], b.x, b.y);
                        mma_bf16(T, ah[m], b.z, b.w);
                        mma_bf16(T, al[m], b.x, b.y);
                    }
                }
            }
            #pragma unroll
            for (int i = 0; i < 6; i++) {
                int n0 = (wid + 16 * i) * 8 + l2;
                #pragma unroll
                for (int m = 0; m < 2; m++) {
                    int row = m * 16 + l4;
                    float* g0 = gs + row * GS_STR + n0;
                    float* g1 = gs + (row + 8) * GS_STR + n0;
                    g0[0] = acc[i][m][0]; g0[1] = acc[i][m][1];
                    g1[0] = acc[i][m][2]; g1[1] = acc[i][m][3];
                    if (i >= 4) {
                        g0[256] = accg[i - 4][m][0]; g0[257] = accg[i - 4][m][1];
                        g1[256] = accg[i - 4][m][2]; g1[257] = accg[i - 4][m][3];
                    }
                }
            }
        }
        __syncthreads();

        // ====== phase 2: gates, h update, base; write bf16 A planes for h ======
        {
            const int row = tid >> 4;
            const int cb  = tid & 15;
            const float* grow = gs + row * GS_STR;
            float* hrow = hs + row * HS_STR;
            float psum = 0.0f;
            #pragma unroll
            for (int i = 0; i < 8; i++) {
                int c = cb * 2 + 32 * i;
                float2 grv = *(const float2*)(grow + c);
                float2 gzv = *(const float2*)(grow + c + 256);
                float2 ghn = *(const float2*)(grow + c + 512);
                float2 gin = *(const float2*)(grow + c + 768);
                float2 hv  = *(const float2*)(hrow + c);
                float n0 = tanhff(gin.x + sigf(grv.x) * ghn.x);
                float n1 = tanhff(gin.y + sigf(grv.y) * ghn.y);
                float z0 = sigf(gzv.x), z1 = sigf(gzv.y);
                float h0 = n0 + z0 * (hv.x - n0);
                float h1 = n1 + z1 * (hv.y - n1);
                *(float2*)(hrow + c) = make_float2(h0, h1);
                float2 wv = *(const float2*)(wh_s + c);
                psum += h0 * wv.x + h1 * wv.y;
                unsigned hi, lo;
                split2(h0, h1, hi, lo);
                Ah32[row * A_U32 + cb + 16 * i] = hi;
                Al32[row * A_U32 + cb + 16 * i] = lo;
            }
            #pragma unroll
            for (int o = 8; o >= 1; o >>= 1)
                psum += __shfl_down_sync(0xffffffffu, psum, o, 16);
            if (cb == 0) base_s[row] = psum + b0;
        }
        __syncthreads();

        // ====== phase 3: logits; write bf16 A planes for prev ======
        #pragma unroll
        for (int rr = 0; rr < 2; rr++) {
            int row = 2 * wid + rr;
            int idx = ((row0 + row) * TSTEPS + t) * EDIM + lane;
            float wbv = (float)targets[idx] * wb_s[lane];
            float v = wbv;
            #pragma unroll
            for (int o = 1; o < 32; o <<= 1) {
                float u = __shfl_up_sync(0xffffffffu, v, o);
                if (lane >= o) v += u;
            }
            float logit = base_s[row] + (v - wbv);
            out[idx] = logit;
            float pl = __shfl_down_sync(0xffffffffu, logit, 1);
            if (!(lane & 1)) {
                unsigned hi, lo;
                split2(logit, pl, hi, lo);
                Ah32[row * A_U32 + 128 + (lane >> 1)] = hi;
                Al32[row * A_U32 + 128 + (lane >> 1)] = lo;
            }
        }
        __syncthreads();
    }
}

extern "C" void kernel_launch(void* const* d_in, const int* in_sizes, int n_in,
                              void* d_out, int out_size)
{
    prep_kernel<<<(NKT * NNT * 32 + 255) / 256, 256>>>(
        (const float*)d_in[8], (const float*)d_in[6]);

    cudaFuncSetAttribute(gru_kernel, cudaFuncAttributeMaxDynamicSharedMemorySize, SMEM_BYTES);
    gru_kernel<<<4096 / BT, NTHR, SMEM_BYTES>>>(
        (const float*)d_in[0], (const int*)d_in[1],
        (const float*)d_in[2], (const float*)d_in[3],
        (const float*)d_in[4], (const float*)d_in[5],
        (const float*)d_in[6], (const float*)d_in[7],
        (const float*)d_in[8], (const float*)d_in[9],
        (const float*)d_in[10], (const float*)d_in[11],
        (float*)d_out);
}

// round 6
// speedup vs baseline: 6.4542x; 1.0114x over previous
#include <cuda_runtime.h>
#include <cuda_bf16.h>

#define NTHR   512
#define BT     32
#define HDIM   256
#define EDIM   32
#define TSTEPS 64
#define G3     768
#define KB     8
#define NKT    18
#define NNT    96

#define HS_STR 260
#define A_PITCH 296            // bf16 elems per A row
#define A_U32   148            // u32 per A row
#define PSTR    20             // partial array stride

// smem offsets (floats)
#define OFF_AHI   0            // 4736
#define OFF_ALO   4736         // 4736
#define OFF_HS    9472         // 8320 (encoder only)
#define OFF_WS    17792        // 2080 (encoder scratch)
#define OFF_BSUM  19872        // 768
#define OFF_BHH   20640        // 768
#define OFF_BIH   21408        // 768
#define OFF_WH    22176        // 256
#define OFF_WB    22432        // 32
#define OFF_PART  22464        // 640
#define OFF_BE1   23104        // 256
#define OFF_BE2   23360        // 256
#define SMEM_FLOATS 23616
#define SMEM_BYTES  (SMEM_FLOATS * 4)   // 94464 bytes

// interleaved W fragments: per (tk,tn,lane): {bh0,bh1,bl0,bl1}
__device__ uint4 g_wfrag[NKT * NNT * 32];

__device__ __forceinline__ unsigned long long pack2(float x) {
    unsigned long long r; asm("mov.b64 %0, {%1,%1};" : "=l"(r) : "f"(x)); return r;
}
__device__ __forceinline__ void fma2(unsigned long long& d, unsigned long long a, unsigned long long b) {
    asm("fma.rn.f32x2 %0, %1, %2, %0;" : "+l"(d) : "l"(a), "l"(b));
}
__device__ __forceinline__ float2 up2(unsigned long long v) {
    float2 f; asm("mov.b64 {%0,%1}, %2;" : "=f"(f.x), "=f"(f.y) : "l"(v)); return f;
}
__device__ __forceinline__ float sigf(float x)  { return 1.0f / (1.0f + __expf(-x)); }
__device__ __forceinline__ float tanhff(float x){ return 1.0f - 2.0f / (__expf(2.0f * x) + 1.0f); }

__device__ __forceinline__ void mma_bf16(float* c, const unsigned* a, unsigned b0, unsigned b1) {
    asm("mma.sync.aligned.m16n8k16.row.col.f32.bf16.bf16.f32 "
        "{%0,%1,%2,%3},{%4,%5,%6,%7},{%8,%9},{%0,%1,%2,%3};"
        : "+f"(c[0]), "+f"(c[1]), "+f"(c[2]), "+f"(c[3])
        : "r"(a[0]), "r"(a[1]), "r"(a[2]), "r"(a[3]), "r"(b0), "r"(b1));
}
__device__ __forceinline__ void ldmat_x4(unsigned* r, unsigned addr) {
    asm volatile("ldmatrix.sync.aligned.m8n8.x4.shared.b16 {%0,%1,%2,%3}, [%4];"
        : "=r"(r[0]), "=r"(r[1]), "=r"(r[2]), "=r"(r[3]) : "r"(addr));
}
__device__ __forceinline__ unsigned packbf(float a, float b) {
    __nv_bfloat16 ha = __float2bfloat16_rn(a), hb = __float2bfloat16_rn(b);
    return (unsigned)__bfloat16_as_ushort(ha) | ((unsigned)__bfloat16_as_ushort(hb) << 16);
}
__device__ __forceinline__ void split2(float a, float b, unsigned& hi, unsigned& lo) {
    __nv_bfloat16 ha = __float2bfloat16_rn(a), hb = __float2bfloat16_rn(b);
    hi = (unsigned)__bfloat16_as_ushort(ha) | ((unsigned)__bfloat16_as_ushort(hb) << 16);
    lo = packbf(a - __bfloat162float(ha), b - __bfloat162float(hb));
}

// ---------- prep: interleaved bf16 hi/lo B-fragments of Wcat = [Whh | Wih] ----------
__global__ void prep_kernel(const float* __restrict__ Whh, const float* __restrict__ Wih) {
    int idx = blockIdx.x * blockDim.x + threadIdx.x;
    if (idx >= NKT * NNT * 32) return;
    int l    = idx & 31;
    int tile = idx >> 5;
    int tn   = tile % NNT;
    int tk   = tile / NNT;
    int n    = tn * 8 + (l >> 2);
    int kb   = tk * 16 + (l & 3) * 2;

    float v[4];
    #pragma unroll
    for (int q = 0; q < 4; q++) {
        int k = kb + (q & 1) + (q >> 1) * 8;
        v[q] = (k < HDIM) ? Whh[n * HDIM + k] : Wih[n * EDIM + (k - HDIM)];
    }
    uint4 o;
    split2(v[0], v[1], o.x, o.z);
    split2(v[2], v[3], o.y, o.w);
    g_wfrag[idx] = o;
}

// ---------- encoder stage (fp32, runs once) ----------
__device__ __forceinline__ void encoder_stage(
    const float* __restrict__ in, int instr,
    const float* __restrict__ Wg, const float* __restrict__ bias_s,
    float* __restrict__ outp, float* __restrict__ ws)
{
    const int tid = threadIdx.x;
    const int c0 = (tid & 63) * 4;
    const int r0 = (tid >> 6) * 4;
    unsigned long long acc[4][2];
    {
        unsigned long long bp0 = *(const unsigned long long*)(bias_s + c0);
        unsigned long long bp1 = *(const unsigned long long*)(bias_s + c0 + 2);
        #pragma unroll
        for (int r = 0; r < 4; r++) { acc[r][0] = bp0; acc[r][1] = bp1; }
    }
    for (int kc = 0; kc < HDIM / KB; kc++) {
        __syncthreads();
        for (int i = tid; i < KB * HDIM; i += NTHR) {
            int j = i >> 3, k = i & 7;
            ws[k * 260 + j] = Wg[j * HDIM + kc * KB + k];
        }
        __syncthreads();
        #pragma unroll
        for (int k = 0; k < KB; k++) {
            ulonglong2 w = *(const ulonglong2*)(ws + k * 260 + c0);
            #pragma unroll
            for (int r = 0; r < 4; r++) {
                unsigned long long a = pack2(in[(r0 + r) * instr + kc * KB + k]);
                fma2(acc[r][0], a, w.x);
                fma2(acc[r][1], a, w.y);
            }
        }
    }
    __syncthreads();
    #pragma unroll
    for (int r = 0; r < 4; r++) {
        float2 v0 = up2(acc[r][0]);
        float2 v1 = up2(acc[r][1]);
        float* o = outp + (r0 + r) * HS_STR + c0;
        o[0] = fmaxf(v0.x, 0.f); o[1] = fmaxf(v0.y, 0.f);
        o[2] = fmaxf(v1.x, 0.f); o[3] = fmaxf(v1.y, 0.f);
    }
}

extern __shared__ float smem[];

__global__ void __launch_bounds__(NTHR, 1)
gru_kernel(const float* __restrict__ x,   const int*   __restrict__ targets,
           const float* __restrict__ We1, const float* __restrict__ be1,
           const float* __restrict__ We2, const float* __restrict__ be2,
           const float* __restrict__ Wih, const float* __restrict__ bih,
           const float* __restrict__ Whh, const float* __restrict__ bhh,
           const float* __restrict__ Wdec,const float* __restrict__ bdec,
           float* __restrict__ out)
{
    unsigned* Ah32 = (unsigned*)(smem + OFF_AHI);
    unsigned* Al32 = (unsigned*)(smem + OFF_ALO);
    float* hs     = smem + OFF_HS;
    float* ws     = smem + OFF_WS;
    float* bsum_s = smem + OFF_BSUM;
    float* bhh_s  = smem + OFF_BHH;
    float* bih_s  = smem + OFF_BIH;
    float* wh_s   = smem + OFF_WH;
    float* wb_s   = smem + OFF_WB;
    float* part   = smem + OFF_PART;
    float* be1_s  = smem + OFF_BE1;
    float* be2_s  = smem + OFF_BE2;

    const int tid  = threadIdx.x;
    const int row0 = blockIdx.x * BT;
    const int wid  = tid >> 5;
    const int lane = tid & 31;

    for (int i = tid; i < G3; i += NTHR) {
        float a = bhh[i], b = bih[i];
        bhh_s[i] = a; bih_s[i] = b; bsum_s[i] = a + b;
    }
    for (int i = tid; i < HDIM; i += NTHR) {
        wh_s[i] = Wdec[i]; be1_s[i] = be1[i]; be2_s[i] = be2[i];
    }
    if (tid < EDIM) wb_s[tid] = Wdec[HDIM + tid];
    const float b0 = bdec[0];

    // stage x tile into A region (stride 260), encoder -> hs
    {
        float* xa = (float*)Ah32;
        for (int i = tid; i < BT * HDIM; i += NTHR) {
            int r = i >> 8, c = i & 255;
            xa[r * 260 + c] = x[(row0 + r) * HDIM + c];
        }
        __syncthreads();
        encoder_stage(xa, 260, We1, be1_s, hs, ws);
        encoder_stage(hs, HS_STR, We2, be2_s, hs, ws);
        __syncthreads();
    }

    const int l4 = lane >> 2;
    const int l2 = (lane & 3) * 2;

    // h state registers: hreg[j][m][q]; rows m*16+l4+8*(q>>1), cols 8wid+128j+l2+(q&1)
    float hreg[2][2][4];
    #pragma unroll
    for (int j = 0; j < 2; j++)
        #pragma unroll
        for (int m = 0; m < 2; m++)
            #pragma unroll
            for (int q = 0; q < 4; q++)
                hreg[j][m][q] = hs[(m * 16 + l4 + 8 * (q >> 1)) * HS_STR
                                   + 8 * wid + 128 * j + l2 + (q & 1)];

    // initial A planes: h0 bf16 hi/lo, prev = 0, pads = 0
    for (int i = tid; i < BT * A_U32; i += NTHR) {
        int r = i / A_U32, cu = i - r * A_U32;
        unsigned hi = 0, lo = 0;
        if (cu < 128) split2(hs[r * HS_STR + 2 * cu], hs[r * HS_STR + 2 * cu + 1], hi, lo);
        Ah32[r * A_U32 + cu] = hi;
        Al32[r * A_U32 + cu] = lo;
    }
    __syncthreads();

    const unsigned aoff = (unsigned)((lane & 15) * A_PITCH + (lane >> 4) * 8) * 2u;
    const unsigned ahi_base = (unsigned)__cvta_generic_to_shared(Ah32) + aoff;
    const unsigned alo_base = (unsigned)__cvta_generic_to_shared(Al32) + aoff;

    for (int t = 0; t < TSTEPS; t++) {
        // ================= GEMM: gates = [h|prev] @ Wcat^T + biases =================
        float acc[6][2][4];
        float accg[2][2][4];
        {
            #pragma unroll
            for (int i = 0; i < 6; i++) {
                int n0 = (wid + 16 * i) * 8 + l2;
                float v0 = (i < 4) ? bsum_s[n0]     : bhh_s[n0];
                float v1 = (i < 4) ? bsum_s[n0 + 1] : bhh_s[n0 + 1];
                #pragma unroll
                for (int m = 0; m < 2; m++) {
                    acc[i][m][0] = v0; acc[i][m][1] = v1;
                    acc[i][m][2] = v0; acc[i][m][3] = v1;
                }
            }
            #pragma unroll 2
            for (int tk = 0; tk < 16; tk++) {
                unsigned ah[2][4], al[2][4];
                #pragma unroll
                for (int m = 0; m < 2; m++) {
                    unsigned off = (unsigned)(m * 16 * A_PITCH + tk * 16) * 2u;
                    ldmat_x4(ah[m], ahi_base + off);
                    ldmat_x4(al[m], alo_base + off);
                }
                #pragma unroll
                for (int i = 0; i < 6; i++) {
                    uint4 b = g_wfrag[(tk * NNT + wid + 16 * i) * 32 + lane];
                    #pragma unroll
                    for (int m = 0; m < 2; m++) {
                        mma_bf16(acc[i][m], ah[m], b.x, b.y);
                        mma_bf16(acc[i][m], ah[m], b.z, b.w);
                        mma_bf16(acc[i][m], al[m], b.x, b.y);
                    }
                }
            }
            #pragma unroll
            for (int i = 0; i < 2; i++) {
                int n0 = (wid + 16 * (4 + i)) * 8 + l2;
                float v0 = bih_s[n0], v1 = bih_s[n0 + 1];
                #pragma unroll
                for (int m = 0; m < 2; m++) {
                    accg[i][m][0] = v0; accg[i][m][1] = v1;
                    accg[i][m][2] = v0; accg[i][m][3] = v1;
                }
            }
            #pragma unroll
            for (int tt = 0; tt < 2; tt++) {
                int tk = 16 + tt;
                unsigned ah[2][4], al[2][4];
                #pragma unroll
                for (int m = 0; m < 2; m++) {
                    unsigned off = (unsigned)(m * 16 * A_PITCH + tk * 16) * 2u;
                    ldmat_x4(ah[m], ahi_base + off);
                    ldmat_x4(al[m], alo_base + off);
                }
                #pragma unroll
                for (int i = 0; i < 6; i++) {
                    uint4 b = g_wfrag[(tk * NNT + wid + 16 * i) * 32 + lane];
                    #pragma unroll
                    for (int m = 0; m < 2; m++) {
                        float* T = (i < 4) ? acc[i][m] : accg[i - 4][m];
                        mma_bf16(T, ah[m], b.x, b.y);
                        mma_bf16(T, ah[m], b.z, b.w);
                        mma_bf16(T, al[m], b.x, b.y);
                    }
                }
            }
        }
        __syncthreads();   // all warps done reading A planes

        // ====== phase 2 (in registers): gates, h update, A-plane write, psum ======
        {
            float ps[4] = {0.f, 0.f, 0.f, 0.f};
            #pragma unroll
            for (int j = 0; j < 2; j++) {
                int cbase = 8 * wid + 128 * j + l2;
                float w0 = wh_s[cbase], w1 = wh_s[cbase + 1];
                int cu = cbase >> 1;
                #pragma unroll
                for (int m = 0; m < 2; m++) {
                    #pragma unroll
                    for (int hf = 0; hf < 2; hf++) {
                        int q0 = hf * 2, q1 = q0 + 1;
                        float rv0 = sigf(acc[j][m][q0]),     rv1 = sigf(acc[j][m][q1]);
                        float zv0 = sigf(acc[2 + j][m][q0]), zv1 = sigf(acc[2 + j][m][q1]);
                        float nv0 = tanhff(accg[j][m][q0] + rv0 * acc[4 + j][m][q0]);
                        float nv1 = tanhff(accg[j][m][q1] + rv1 * acc[4 + j][m][q1]);
                        float h0 = nv0 + zv0 * (hreg[j][m][q0] - nv0);
                        float h1 = nv1 + zv1 * (hreg[j][m][q1] - nv1);
                        hreg[j][m][q0] = h0; hreg[j][m][q1] = h1;
                        ps[m * 2 + hf] += h0 * w0 + h1 * w1;
                        unsigned hi, lo;
                        split2(h0, h1, hi, lo);
                        int row = m * 16 + l4 + 8 * hf;
                        Ah32[row * A_U32 + cu] = hi;
                        Al32[row * A_U32 + cu] = lo;
                    }
                }
            }
            #pragma unroll
            for (int q = 0; q < 4; q++) {
                ps[q] += __shfl_xor_sync(0xffffffffu, ps[q], 1);
                ps[q] += __shfl_xor_sync(0xffffffffu, ps[q], 2);
            }
            if ((lane & 3) == 0) {
                part[l4 * PSTR + wid]        = ps[0];
                part[(l4 + 8) * PSTR + wid]  = ps[1];
                part[(l4 + 16) * PSTR + wid] = ps[2];
                part[(l4 + 24) * PSTR + wid] = ps[3];
            }
        }
        __syncthreads();

        // ====== phase 3: base reduce + logits; write bf16 A planes for prev ======
        #pragma unroll
        for (int rr = 0; rr < 2; rr++) {
            int row = 2 * wid + rr;
            const float* pp = part + row * PSTR;
            float4 p0 = *(const float4*)pp;
            float4 p1 = *(const float4*)(pp + 4);
            float4 p2 = *(const float4*)(pp + 8);
            float4 p3 = *(const float4*)(pp + 12);
            float base = ((p0.x + p0.y) + (p0.z + p0.w)) + ((p1.x + p1.y) + (p1.z + p1.w))
                       + ((p2.x + p2.y) + (p2.z + p2.w)) + ((p3.x + p3.y) + (p3.z + p3.w)) + b0;

            int idx = ((row0 + row) * TSTEPS + t) * EDIM + lane;
            float wbv = (float)targets[idx] * wb_s[lane];
            float v = wbv;
            #pragma unroll
            for (int o = 1; o < 32; o <<= 1) {
                float u = __shfl_up_sync(0xffffffffu, v, o);
                if (lane >= o) v += u;
            }
            float logit = base + (v - wbv);
            out[idx] = logit;
            float pl = __shfl_down_sync(0xffffffffu, logit, 1);
            if (!(lane & 1)) {
                unsigned hi, lo;
                split2(logit, pl, hi, lo);
                Ah32[row * A_U32 + 128 + (lane >> 1)] = hi;
                Al32[row * A_U32 + 128 + (lane >> 1)] = lo;
            }
        }
        __syncthreads();
    }
}

extern "C" void kernel_launch(void* const* d_in, const int* in_sizes, int n_in,
                              void* d_out, int out_size)
{
    prep_kernel<<<(NKT * NNT * 32 + 255) / 256, 256>>>(
        (const float*)d_in[8], (const float*)d_in[6]);

    cudaFuncSetAttribute(gru_kernel, cudaFuncAttributeMaxDynamicSharedMemorySize, SMEM_BYTES);
    gru_kernel<<<4096 / BT, NTHR, SMEM_BYTES>>>(
        (const float*)d_in[0], (const int*)d_in[1],
        (const float*)d_in[2], (const float*)d_in[3],
        (const float*)d_in[4], (const float*)d_in[5],
        (const float*)d_in[6], (const float*)d_in[7],
        (const float*)d_in[8], (const float*)d_in[9],
        (const float*)d_in[10], (const float*)d_in[11],
        (float*)d_out);
}

// round 7
// speedup vs baseline: 7.0580x; 1.0936x over previous
#include <cuda_runtime.h>
#include <cuda_bf16.h>

#define NTHR   1024
#define BT     32
#define HDIM   256
#define EDIM   32
#define TSTEPS 64
#define G3     768
#define KB     8
#define NKT    18
#define NNT    96

#define HS_STR 260
#define A_PITCH 296            // bf16 elems per A row
#define A_U32   148            // u32 per A row
#define PSTR    36             // partial array stride (32 warps + pad)

// smem offsets (floats)
#define OFF_AHI   0            // 4736
#define OFF_ALO   4736         // 4736
#define OFF_HS    9472         // 8320
#define OFF_WS    17792        // 2080 (encoder scratch)
#define OFF_BSUM  19872        // 768
#define OFF_BHH   20640        // 768
#define OFF_BIH   21408        // 768
#define OFF_WH    22176        // 256
#define OFF_WB    22432        // 32
#define OFF_PART  22464        // 32*36 = 1152
#define OFF_BE1   23616        // 256
#define OFF_BE2   23872        // 256
#define SMEM_FLOATS 24128
#define SMEM_BYTES  (SMEM_FLOATS * 4)   // 96512 bytes

// interleaved W fragments: per (tk,tn,lane): {bh0,bh1,bl0,bl1}
__device__ uint4 g_wfrag[NKT * NNT * 32];

__device__ __forceinline__ unsigned long long pack2(float x) {
    unsigned long long r; asm("mov.b64 %0, {%1,%1};" : "=l"(r) : "f"(x)); return r;
}
__device__ __forceinline__ void fma2(unsigned long long& d, unsigned long long a, unsigned long long b) {
    asm("fma.rn.f32x2 %0, %1, %2, %0;" : "+l"(d) : "l"(a), "l"(b));
}
__device__ __forceinline__ float2 up2(unsigned long long v) {
    float2 f; asm("mov.b64 {%0,%1}, %2;" : "=f"(f.x), "=f"(f.y) : "l"(v)); return f;
}
__device__ __forceinline__ float sigf(float x)  { return 1.0f / (1.0f + __expf(-x)); }
__device__ __forceinline__ float tanhff(float x){ return 1.0f - 2.0f / (__expf(2.0f * x) + 1.0f); }

__device__ __forceinline__ void mma_bf16(float* c, const unsigned* a, unsigned b0, unsigned b1) {
    asm("mma.sync.aligned.m16n8k16.row.col.f32.bf16.bf16.f32 "
        "{%0,%1,%2,%3},{%4,%5,%6,%7},{%8,%9},{%0,%1,%2,%3};"
        : "+f"(c[0]), "+f"(c[1]), "+f"(c[2]), "+f"(c[3])
        : "r"(a[0]), "r"(a[1]), "r"(a[2]), "r"(a[3]), "r"(b0), "r"(b1));
}
__device__ __forceinline__ void ldmat_x4(unsigned* r, unsigned addr) {
    asm volatile("ldmatrix.sync.aligned.m8n8.x4.shared.b16 {%0,%1,%2,%3}, [%4];"
        : "=r"(r[0]), "=r"(r[1]), "=r"(r[2]), "=r"(r[3]) : "r"(addr));
}
__device__ __forceinline__ unsigned packbf(float a, float b) {
    __nv_bfloat16 ha = __float2bfloat16_rn(a), hb = __float2bfloat16_rn(b);
    return (unsigned)__bfloat16_as_ushort(ha) | ((unsigned)__bfloat16_as_ushort(hb) << 16);
}
__device__ __forceinline__ void split2(float a, float b, unsigned& hi, unsigned& lo) {
    __nv_bfloat16 ha = __float2bfloat16_rn(a), hb = __float2bfloat16_rn(b);
    hi = (unsigned)__bfloat16_as_ushort(ha) | ((unsigned)__bfloat16_as_ushort(hb) << 16);
    lo = packbf(a - __bfloat162float(ha), b - __bfloat162float(hb));
}

// ---------- prep: interleaved bf16 hi/lo B-fragments of Wcat = [Whh | Wih] ----------
__global__ void prep_kernel(const float* __restrict__ Whh, const float* __restrict__ Wih) {
    int idx = blockIdx.x * blockDim.x + threadIdx.x;
    if (idx >= NKT * NNT * 32) return;
    int l    = idx & 31;
    int tile = idx >> 5;
    int tn   = tile % NNT;
    int tk   = tile / NNT;
    int n    = tn * 8 + (l >> 2);
    int kb   = tk * 16 + (l & 3) * 2;

    float v[4];
    #pragma unroll
    for (int q = 0; q < 4; q++) {
        int k = kb + (q & 1) + (q >> 1) * 8;
        v[q] = (k < HDIM) ? Whh[n * HDIM + k] : Wih[n * EDIM + (k - HDIM)];
    }
    uint4 o;
    split2(v[0], v[1], o.x, o.z);
    split2(v[2], v[3], o.y, o.w);
    g_wfrag[idx] = o;
}

// ---------- encoder stage (fp32, runs once; 1024 threads) ----------
__device__ __forceinline__ void encoder_stage(
    const float* __restrict__ in, int instr,
    const float* __restrict__ Wg, const float* __restrict__ bias_s,
    float* __restrict__ outp, float* __restrict__ ws)
{
    const int tid = threadIdx.x;
    const int c0 = (tid & 63) * 4;
    const int r0 = (tid >> 6) * 2;     // 16 row groups x 2 rows
    unsigned long long acc[2][2];
    {
        unsigned long long bp0 = *(const unsigned long long*)(bias_s + c0);
        unsigned long long bp1 = *(const unsigned long long*)(bias_s + c0 + 2);
        #pragma unroll
        for (int r = 0; r < 2; r++) { acc[r][0] = bp0; acc[r][1] = bp1; }
    }
    for (int kc = 0; kc < HDIM / KB; kc++) {
        __syncthreads();
        for (int i = tid; i < KB * HDIM; i += NTHR) {
            int j = i >> 3, k = i & 7;
            ws[k * 260 + j] = Wg[j * HDIM + kc * KB + k];
        }
        __syncthreads();
        #pragma unroll
        for (int k = 0; k < KB; k++) {
            ulonglong2 w = *(const ulonglong2*)(ws + k * 260 + c0);
            #pragma unroll
            for (int r = 0; r < 2; r++) {
                unsigned long long a = pack2(in[(r0 + r) * instr + kc * KB + k]);
                fma2(acc[r][0], a, w.x);
                fma2(acc[r][1], a, w.y);
            }
        }
    }
    __syncthreads();
    #pragma unroll
    for (int r = 0; r < 2; r++) {
        float2 v0 = up2(acc[r][0]);
        float2 v1 = up2(acc[r][1]);
        float* o = outp + (r0 + r) * HS_STR + c0;
        o[0] = fmaxf(v0.x, 0.f); o[1] = fmaxf(v0.y, 0.f);
        o[2] = fmaxf(v1.x, 0.f); o[3] = fmaxf(v1.y, 0.f);
    }
}

extern __shared__ float smem[];

__global__ void __launch_bounds__(NTHR, 1)
gru_kernel(const float* __restrict__ x,   const int*   __restrict__ targets,
           const float* __restrict__ We1, const float* __restrict__ be1,
           const float* __restrict__ We2, const float* __restrict__ be2,
           const float* __restrict__ Wih, const float* __restrict__ bih,
           const float* __restrict__ Whh, const float* __restrict__ bhh,
           const float* __restrict__ Wdec,const float* __restrict__ bdec,
           float* __restrict__ out)
{
    unsigned* Ah32 = (unsigned*)(smem + OFF_AHI);
    unsigned* Al32 = (unsigned*)(smem + OFF_ALO);
    float* hs     = smem + OFF_HS;
    float* ws     = smem + OFF_WS;
    float* bsum_s = smem + OFF_BSUM;
    float* bhh_s  = smem + OFF_BHH;
    float* bih_s  = smem + OFF_BIH;
    float* wh_s   = smem + OFF_WH;
    float* wb_s   = smem + OFF_WB;
    float* part   = smem + OFF_PART;
    float* be1_s  = smem + OFF_BE1;
    float* be2_s  = smem + OFF_BE2;

    const int tid  = threadIdx.x;
    const int row0 = blockIdx.x * BT;
    const int wid  = tid >> 5;     // 0..31
    const int lane = tid & 31;

    for (int i = tid; i < G3; i += NTHR) {
        float a = bhh[i], b = bih[i];
        bhh_s[i] = a; bih_s[i] = b; bsum_s[i] = a + b;
    }
    for (int i = tid; i < HDIM; i += NTHR) {
        wh_s[i] = Wdec[i]; be1_s[i] = be1[i]; be2_s[i] = be2[i];
    }
    if (tid < EDIM) wb_s[tid] = Wdec[HDIM + tid];
    const float b0 = bdec[0];

    // stage x tile into A region (contiguous 9472 floats, stride 260), encoder -> hs
    {
        float* xa = (float*)Ah32;
        for (int i = tid; i < BT * HDIM; i += NTHR) {
            int r = i >> 8, c = i & 255;
            xa[r * 260 + c] = x[(row0 + r) * HDIM + c];
        }
        __syncthreads();
        encoder_stage(xa, 260, We1, be1_s, hs, ws);
        encoder_stage(hs, HS_STR, We2, be2_s, hs, ws);
        __syncthreads();
    }

    // initial A planes: h0 bf16 hi/lo, prev = 0, pads = 0
    for (int i = tid; i < BT * A_U32; i += NTHR) {
        int r = i / A_U32, cu = i - r * A_U32;
        unsigned hi = 0, lo = 0;
        if (cu < 128) split2(hs[r * HS_STR + 2 * cu], hs[r * HS_STR + 2 * cu + 1], hi, lo);
        Ah32[r * A_U32 + cu] = hi;
        Al32[r * A_U32 + cu] = lo;
    }
    __syncthreads();

    const int l4 = lane >> 2;
    const int l2 = (lane & 3) * 2;
    const unsigned aoff = (unsigned)((lane & 15) * A_PITCH + (lane >> 4) * 8) * 2u;
    const unsigned ahi_base = (unsigned)__cvta_generic_to_shared(Ah32) + aoff;
    const unsigned alo_base = (unsigned)__cvta_generic_to_shared(Al32) + aoff;

    for (int t = 0; t < TSTEPS; t++) {
        // ================= GEMM: gates = [h|prev] @ Wcat^T + biases =================
        // warp w owns n-tiles {w, w+32, w+64}: r, z, hn(+inn) for hidden cols [8w, 8w+8)
        float acc[3][2][4];
        float accg[2][4];
        {
            #pragma unroll
            for (int i = 0; i < 3; i++) {
                int n0 = (wid + 32 * i) * 8 + l2;
                float v0 = (i < 2) ? bsum_s[n0]     : bhh_s[n0];
                float v1 = (i < 2) ? bsum_s[n0 + 1] : bhh_s[n0 + 1];
                #pragma unroll
                for (int m = 0; m < 2; m++) {
                    acc[i][m][0] = v0; acc[i][m][1] = v1;
                    acc[i][m][2] = v0; acc[i][m][3] = v1;
                }
            }
            {
                int n0 = (wid + 64) * 8 + l2;
                float v0 = bih_s[n0], v1 = bih_s[n0 + 1];
                #pragma unroll
                for (int m = 0; m < 2; m++) {
                    accg[m][0] = v0; accg[m][1] = v1;
                    accg[m][2] = v0; accg[m][3] = v1;
                }
            }
            #pragma unroll 2
            for (int tk = 0; tk < 16; tk++) {
                unsigned ah[2][4], al[2][4];
                #pragma unroll
                for (int m = 0; m < 2; m++) {
                    unsigned off = (unsigned)(m * 16 * A_PITCH + tk * 16) * 2u;
                    ldmat_x4(ah[m], ahi_base + off);
                    ldmat_x4(al[m], alo_base + off);
                }
                #pragma unroll
                for (int i = 0; i < 3; i++) {
                    uint4 b = g_wfrag[(tk * NNT + wid + 32 * i) * 32 + lane];
                    #pragma unroll
                    for (int m = 0; m < 2; m++) {
                        mma_bf16(acc[i][m], ah[m], b.x, b.y);
                        mma_bf16(acc[i][m], ah[m], b.z, b.w);
                        mma_bf16(acc[i][m], al[m], b.x, b.y);
                    }
                }
            }
            #pragma unroll
            for (int tt = 0; tt < 2; tt++) {
                int tk = 16 + tt;
                unsigned ah[2][4], al[2][4];
                #pragma unroll
                for (int m = 0; m < 2; m++) {
                    unsigned off = (unsigned)(m * 16 * A_PITCH + tk * 16) * 2u;
                    ldmat_x4(ah[m], ahi_base + off);
                    ldmat_x4(al[m], alo_base + off);
                }
                #pragma unroll
                for (int i = 0; i < 3; i++) {
                    uint4 b = g_wfrag[(tk * NNT + wid + 32 * i) * 32 + lane];
                    #pragma unroll
                    for (int m = 0; m < 2; m++) {
                        float* T = (i < 2) ? acc[i][m] : accg[m];
                        mma_bf16(T, ah[m], b.x, b.y);
                        mma_bf16(T, ah[m], b.z, b.w);
                        mma_bf16(T, al[m], b.x, b.y);
                    }
                }
            }
        }
        __syncthreads();

        // ====== phase 2: gates, h update (smem), A-plane write, psum ======
        {
            const int cbase = 8 * wid + l2;
            const float w0 = wh_s[cbase], w1 = wh_s[cbase + 1];
            const int cu = 4 * wid + (lane & 3);
            float ps[4];
            #pragma unroll
            for (int m = 0; m < 2; m++) {
                #pragma unroll
                for (int hf = 0; hf < 2; hf++) {
                    int g = 2 * m + hf, q0 = 2 * hf, q1 = q0 + 1;
                    int row = 8 * g + l4;
                    float2 hv = *(const float2*)(hs + row * HS_STR + cbase);
                    float rv0 = sigf(acc[0][m][q0]), rv1 = sigf(acc[0][m][q1]);
                    float zv0 = sigf(acc[1][m][q0]), zv1 = sigf(acc[1][m][q1]);
                    float nv0 = tanhff(accg[m][q0] + rv0 * acc[2][m][q0]);
                    float nv1 = tanhff(accg[m][q1] + rv1 * acc[2][m][q1]);
                    float h0 = nv0 + zv0 * (hv.x - nv0);
                    float h1 = nv1 + zv1 * (hv.y - nv1);
                    *(float2*)(hs + row * HS_STR + cbase) = make_float2(h0, h1);
                    ps[g] = h0 * w0 + h1 * w1;
                    unsigned hi, lo;
                    split2(h0, h1, hi, lo);
                    Ah32[row * A_U32 + cu] = hi;
                    Al32[row * A_U32 + cu] = lo;
                }
            }
            #pragma unroll
            for (int g = 0; g < 4; g++) {
                ps[g] += __shfl_xor_sync(0xffffffffu, ps[g], 1);
                ps[g] += __shfl_xor_sync(0xffffffffu, ps[g], 2);
            }
            if ((lane & 3) == 0) {
                #pragma unroll
                for (int g = 0; g < 4; g++)
                    part[(8 * g + l4) * PSTR + wid] = ps[g];
            }
        }
        __syncthreads();

        // ====== phase 3: base reduce + logits; write bf16 A planes for prev ======
        {
            int row = wid;
            float pv = part[row * PSTR + lane];
            #pragma unroll
            for (int o = 16; o >= 1; o >>= 1)
                pv += __shfl_xor_sync(0xffffffffu, pv, o);
            float base = pv + b0;

            int idx = ((row0 + row) * TSTEPS + t) * EDIM + lane;
            float wbv = (float)targets[idx] * wb_s[lane];
            float v = wbv;
            #pragma unroll
            for (int o = 1; o < 32; o <<= 1) {
                float u = __shfl_up_sync(0xffffffffu, v, o);
                if (lane >= o) v += u;
            }
            float logit = base + (v - wbv);
            out[idx] = logit;
            float pl = __shfl_down_sync(0xffffffffu, logit, 1);
            if (!(lane & 1)) {
                unsigned hi, lo;
                split2(logit, pl, hi, lo);
                Ah32[row * A_U32 + 128 + (lane >> 1)] = hi;
                Al32[row * A_U32 + 128 + (lane >> 1)] = lo;
            }
        }
        __syncthreads();
    }
}

extern "C" void kernel_launch(void* const* d_in, const int* in_sizes, int n_in,
                              void* d_out, int out_size)
{
    prep_kernel<<<(NKT * NNT * 32 + 255) / 256, 256>>>(
        (const float*)d_in[8], (const float*)d_in[6]);

    cudaFuncSetAttribute(gru_kernel, cudaFuncAttributeMaxDynamicSharedMemorySize, SMEM_BYTES);
    gru_kernel<<<4096 / BT, NTHR, SMEM_BYTES>>>(
        (const float*)d_in[0], (const int*)d_in[1],
        (const float*)d_in[2], (const float*)d_in[3],
        (const float*)d_in[4], (const float*)d_in[5],
        (const float*)d_in[6], (const float*)d_in[7],
        (const float*)d_in[8], (const float*)d_in[9],
        (const float*)d_in[10], (const float*)d_in[11],
        (float*)d_out);
}